// round 1
// baseline (speedup 1.0000x reference)
#include <cuda_runtime.h>
#include <math.h>

#define NMAX 20000
#define CDIM 32

// Scatter-add accumulators (33 MB total, fits in L2)
__device__ float g_A0[NMAX * CDIM];          // [N,C]
__device__ float g_A1[NMAX * CDIM * 3];      // [N,C,3]
__device__ float g_A2[NMAX * CDIM * 9];      // [N,C,3,3]

// ---------------------------------------------------------------------------
// Zero accumulators
// ---------------------------------------------------------------------------
__global__ void zero_kernel(int n0) {
    int i = blockIdx.x * blockDim.x + threadIdx.x;
    int stride = gridDim.x * blockDim.x;
    for (int k = i; k < n0; k += stride) g_A0[k] = 0.0f;
    for (int k = i; k < n0 * 3; k += stride) g_A1[k] = 0.0f;
    for (int k = i; k < n0 * 9; k += stride) g_A2[k] = 0.0f;
}

// ---------------------------------------------------------------------------
// Edge kernel: warp per edge, lane = channel.
// rbf -> per-path radial filters w[11] -> analytic moment contractions ->
// atomicAdd scatter into g_A0/1/2.
// ---------------------------------------------------------------------------
__global__ void edge_kernel(const float* __restrict__ node0,
                            const float* __restrict__ node1,
                            const float* __restrict__ node2,
                            const float* __restrict__ rij,
                            const float* __restrict__ Wrad,
                            const int* __restrict__ idx_i,
                            const int* __restrict__ idx_j,
                            int E)
{
    __shared__ float sW[11 * 8 * 32];   // Wrad [11][8][32]
    for (int i = threadIdx.x; i < 11 * 8 * 32; i += blockDim.x) sW[i] = Wrad[i];
    __syncthreads();

    int e = blockIdx.x * (blockDim.x >> 5) + (threadIdx.x >> 5);
    if (e >= E) return;
    int c = threadIdx.x & 31;

    float rx = rij[3 * e + 0];
    float ry = rij[3 * e + 1];
    float rz = rij[3 * e + 2];
    float dd = rx * rx + ry * ry + rz * rz + 1e-12f;
    float dist = sqrtf(dd);
    float inv = 1.0f / dist;
    float h[3] = { rx * inv, ry * inv, rz * inv };

    float u = fminf(dist * (1.0f / 5.0f), 1.0f);
    float fc = 0.5f * (cosf(3.14159265358979323846f * u) + 1.0f);

    float w[11];
#pragma unroll
    for (int p = 0; p < 11; p++) w[p] = 0.0f;
#pragma unroll
    for (int b = 0; b < 8; b++) {
        float cb = 0.5f + (float)b * (4.5f / 7.0f);
        float dl = dist - cb;
        float rb = expf(-4.0f * dl * dl) * fc;
#pragma unroll
        for (int p = 0; p < 11; p++) w[p] += rb * sW[(p * 8 + b) * 32 + c];
    }

    int j = idx_j[e];
    float g0 = node0[j * 32 + c];
    const float* p1 = node1 + (size_t)(j * 32 + c) * 3;
    float g1[3];
#pragma unroll
    for (int a = 0; a < 3; a++) g1[a] = p1[a];
    const float* p2 = node2 + (size_t)(j * 32 + c) * 9;
    float g2[9];
#pragma unroll
    for (int k = 0; k < 9; k++) g2[k] = p2[k];

    float d1 = g1[0] * h[0] + g1[1] * h[1] + g1[2] * h[2];
    float d2[3];
#pragma unroll
    for (int a = 0; a < 3; a++)
        d2[a] = g2[a * 3 + 0] * h[0] + g2[a * 3 + 1] * h[1] + g2[a * 3 + 2] * h[2];
    float q = d2[0] * h[0] + d2[1] * h[1] + d2[2] * h[2];

    int i = idx_i[e];

    // way-0 message
    atomicAdd(&g_A0[i * 32 + c], g0 * w[0] + d1 * w[4] + q * w[9]);

    // way-1 message: msg1[a] = (g0*w1 + d1*w6)*h[a] + g1[a]*w3 + d2[a]*w8
    float* A1 = g_A1 + (size_t)(i * 32 + c) * 3;
    float s01 = g0 * w[1] + d1 * w[6];
#pragma unroll
    for (int a = 0; a < 3; a++)
        atomicAdd(&A1[a], s01 * h[a] + g1[a] * w[3] + d2[a] * w[8]);

    // way-2 message: msg2[a][b] = (g0*w2*h[a] + g1[a]*w5 + d2[a]*w10)*h[b] + g2[ab]*w7
    float* A2 = g_A2 + (size_t)(i * 32 + c) * 9;
    float gw2 = g0 * w[2];
#pragma unroll
    for (int a = 0; a < 3; a++) {
        float pre = gw2 * h[a] + g1[a] * w[5] + d2[a] * w[10];
#pragma unroll
        for (int b = 0; b < 3; b++)
            atomicAdd(&A2[a * 3 + b], pre * h[b] + g2[a * 3 + b] * w[7]);
    }
}

// ---------------------------------------------------------------------------
// Node kernel: warp per node, lane doubles as channel c (for staging) and
// output channel d (for matvecs). Weights U/V in shared; Wg via L1.
// ---------------------------------------------------------------------------
__global__ void node_kernel(const float* __restrict__ node0,
                            const float* __restrict__ node1,
                            const float* __restrict__ node2,
                            const float* __restrict__ U,
                            const float* __restrict__ V,
                            const float* __restrict__ Wg,
                            float* __restrict__ out,
                            int N)
{
    extern __shared__ float sh[];
    float* sWm = sh;                                  // 11*1024 floats: U0..U2, V0..V7
    int nwarps = blockDim.x >> 5;
    float* sX = sh + 11 * 1024;                       // [nwarps][27][32]
    float* sY = sX + nwarps * 27 * 32;                // [nwarps][32]

    for (int i = threadIdx.x; i < 3 * 1024; i += blockDim.x) sWm[i] = U[i];
    for (int i = threadIdx.x; i < 8 * 1024; i += blockDim.x) sWm[3 * 1024 + i] = V[i];
    __syncthreads();

    int warp = threadIdx.x >> 5;
    int lane = threadIdx.x & 31;
    int n = blockIdx.x * nwarps + warp;
    if (n >= N) return;

    float* Xs = sX + warp * 27 * 32;
    const float norm = 1.0f / 16.0f;

    float a0 = g_A0[n * 32 + lane] * norm;
    float a1[3];
#pragma unroll
    for (int a = 0; a < 3; a++) a1[a] = g_A1[(size_t)(n * 32 + lane) * 3 + a] * norm;
    float a2[9];
#pragma unroll
    for (int k = 0; k < 9; k++) a2[k] = g_A2[(size_t)(n * 32 + lane) * 9 + k] * norm;

    float s1 = a1[0] * a1[0] + a1[1] * a1[1] + a1[2] * a1[2];
    float s2 = 0.0f;
#pragma unroll
    for (int k = 0; k < 9; k++) s2 += a2[k] * a2[k];
    float t[3];
#pragma unroll
    for (int b = 0; b < 3; b++)
        t[b] = a1[0] * a2[0 * 3 + b] + a1[1] * a2[1 * 3 + b] + a1[2] * a2[2 * 3 + b];
    float r[9];
#pragma unroll
    for (int a = 0; a < 3; a++)
#pragma unroll
        for (int b = 0; b < 3; b++)
            r[a * 3 + b] = a2[a * 3 + 0] * a2[0 * 3 + b]
                         + a2[a * 3 + 1] * a2[1 * 3 + b]
                         + a2[a * 3 + 2] * a2[2 * 3 + b];

    // stage raw x vectors (derived products recomputed on the fly in matvec)
    Xs[0 * 32 + lane] = a0;
    Xs[1 * 32 + lane] = s1;
    Xs[2 * 32 + lane] = s2;
#pragma unroll
    for (int a = 0; a < 3; a++) { Xs[(3 + a) * 32 + lane] = a1[a]; Xs[(6 + a) * 32 + lane] = t[a]; }
#pragma unroll
    for (int k = 0; k < 9; k++) { Xs[(9 + k) * 32 + lane] = a2[k]; Xs[(18 + k) * 32 + lane] = r[k]; }
    __syncwarp();

    int d = lane;
    float y0 = 0.0f;
    float y1[3] = {0.0f, 0.0f, 0.0f};
    float y2[9] = {0.0f, 0.0f, 0.0f, 0.0f, 0.0f, 0.0f, 0.0f, 0.0f, 0.0f};

#pragma unroll 4
    for (int c = 0; c < 32; c++) {
        int wi = c * 32 + d;
        float xa0 = Xs[c];
        float xs1 = Xs[32 + c];
        float xs2 = Xs[64 + c];

        // y0: U0, V0, V3, V6   (V[k] -> sWm[(3+k)*1024])
        y0 += xa0 * sWm[0 * 1024 + wi]
            + (xa0 * xa0) * sWm[3 * 1024 + wi]
            + xs1 * sWm[6 * 1024 + wi]
            + xs2 * sWm[9 * 1024 + wi];

        // y1: U1, V1, V5
        float wU1 = sWm[1 * 1024 + wi];
        float wV1 = sWm[4 * 1024 + wi];
        float wV5 = sWm[8 * 1024 + wi];
        float xa1[3];
#pragma unroll
        for (int a = 0; a < 3; a++) {
            xa1[a] = Xs[(3 + a) * 32 + c];
            float xt = Xs[(6 + a) * 32 + c];
            y1[a] += xa1[a] * wU1 + (xa0 * xa1[a]) * wV1 + xt * wV5;
        }

        // y2: U2, V2, V4, V7
        float wU2 = sWm[2 * 1024 + wi];
        float wV2 = sWm[5 * 1024 + wi];
        float wV4 = sWm[7 * 1024 + wi];
        float wV7 = sWm[10 * 1024 + wi];
#pragma unroll
        for (int a = 0; a < 3; a++) {
#pragma unroll
            for (int b = 0; b < 3; b++) {
                int k = a * 3 + b;
                float xa2 = Xs[(9 + k) * 32 + c];
                float xr = Xs[(18 + k) * 32 + c];
                y2[k] += xa2 * wU2 + (xa0 * xa2) * wV2 + (xa1[a] * xa1[b]) * wV4 + xr * wV7;
            }
        }
    }

    // gates: silu(y0 @ Wg[k]) ; y0 staged through shared, Wg via L1
    sY[warp * 32 + d] = y0;
    __syncwarp();
    const float* Ys = sY + warp * 32;
    float gp0 = 0.0f, gp1 = 0.0f, gp2 = 0.0f;
#pragma unroll 4
    for (int c = 0; c < 32; c++) {
        float yc = Ys[c];
        gp0 += yc * __ldg(&Wg[0 * 1024 + c * 32 + d]);
        gp1 += yc * __ldg(&Wg[1 * 1024 + c * 32 + d]);
        gp2 += yc * __ldg(&Wg[2 * 1024 + c * 32 + d]);
    }
    float gate0 = gp0 / (1.0f + expf(-gp0));
    float gate1 = gp1 / (1.0f + expf(-gp1));
    float gate2 = gp2 / (1.0f + expf(-gp2));

    // outputs: new0 | new1 | new2 concatenated
    float* out0 = out;
    float* out1 = out + (size_t)N * 32;
    float* out2 = out + (size_t)N * 32 * 4;

    out0[n * 32 + d] = node0[n * 32 + d] + gate0;
    const float* n1p = node1 + (size_t)(n * 32 + d) * 3;
    float* o1p = out1 + (size_t)(n * 32 + d) * 3;
#pragma unroll
    for (int a = 0; a < 3; a++) o1p[a] = n1p[a] + y1[a] * gate1;
    const float* n2p = node2 + (size_t)(n * 32 + d) * 9;
    float* o2p = out2 + (size_t)(n * 32 + d) * 9;
#pragma unroll
    for (int k = 0; k < 9; k++) o2p[k] = n2p[k] + y2[k] * gate2;
}

// ---------------------------------------------------------------------------
// Launch
// ---------------------------------------------------------------------------
extern "C" void kernel_launch(void* const* d_in, const int* in_sizes, int n_in,
                              void* d_out, int out_size)
{
    const float* node0 = (const float*)d_in[0];
    const float* node1 = (const float*)d_in[1];
    const float* node2 = (const float*)d_in[2];
    const float* rij   = (const float*)d_in[3];
    const float* Wrad  = (const float*)d_in[4];
    const float* U     = (const float*)d_in[5];
    const float* V     = (const float*)d_in[6];
    const float* Wg    = (const float*)d_in[7];
    const int*   idx_i = (const int*)d_in[8];
    const int*   idx_j = (const int*)d_in[9];
    float* out = (float*)d_out;

    int N = in_sizes[0] / 32;
    int E = in_sizes[8];

    int node_warps = 8;
    int node_smem = (11 * 1024 + node_warps * 27 * 32 + node_warps * 32) * (int)sizeof(float);
    cudaFuncSetAttribute(node_kernel, cudaFuncAttributeMaxDynamicSharedMemorySize, node_smem);

    zero_kernel<<<2048, 256>>>(N * 32);
    edge_kernel<<<(E + 7) / 8, 256>>>(node0, node1, node2, rij, Wrad, idx_i, idx_j, E);
    node_kernel<<<(N + node_warps - 1) / node_warps, 32 * node_warps, node_smem>>>(
        node0, node1, node2, U, V, Wg, out, N);
}

// round 2
// speedup vs baseline: 1.8637x; 1.8637x over previous
#include <cuda_runtime.h>
#include <math.h>

#define NMAX 20000
#define EMAX 320000

// CSR build scratch
__device__ int g_deg[NMAX];
__device__ int g_off[NMAX + 1];
__device__ int g_cur[NMAX];
__device__ int g_edge[EMAX];

// ---------------------------------------------------------------------------
__global__ void zero_deg_kernel(int N) {
    int i = blockIdx.x * blockDim.x + threadIdx.x;
    if (i < N) g_deg[i] = 0;
}

__global__ void hist_kernel(const int* __restrict__ idx_i, int E) {
    int e = blockIdx.x * blockDim.x + threadIdx.x;
    if (e < E) atomicAdd(&g_deg[idx_i[e]], 1);
}

// Single-block exclusive scan over N degrees -> g_off, g_cur
__global__ void scan_kernel(int N, int E) {
    __shared__ int ssum[1024];
    int t = threadIdx.x;
    int chunk = (N + 1023) / 1024;
    int base = t * chunk;
    int s = 0;
    for (int k = 0; k < chunk; k++) {
        int idx = base + k;
        if (idx < N) s += g_deg[idx];
    }
    ssum[t] = s;
    __syncthreads();
    // inclusive scan (Hillis-Steele)
    for (int off = 1; off < 1024; off <<= 1) {
        int v = (t >= off) ? ssum[t - off] : 0;
        __syncthreads();
        ssum[t] += v;
        __syncthreads();
    }
    int run = ssum[t] - s;   // exclusive prefix for this thread's chunk
    for (int k = 0; k < chunk; k++) {
        int idx = base + k;
        if (idx < N) {
            int d = g_deg[idx];
            g_off[idx] = run;
            g_cur[idx] = run;
            run += d;
        }
    }
    if (t == 0) g_off[N] = E;
}

__global__ void scatter_kernel(const int* __restrict__ idx_i, int E) {
    int e = blockIdx.x * blockDim.x + threadIdx.x;
    if (e < E) {
        int p = atomicAdd(&g_cur[idx_i[e]], 1);
        g_edge[p] = e;
    }
}

// ---------------------------------------------------------------------------
// Fused kernel: warp per node.
// Phase 1: iterate incoming edges (CSR), accumulate messages in registers.
// Phase 2: self-interaction (U/V matvecs), gates, residual, output.
// ---------------------------------------------------------------------------
#define NWARPS 8

__global__ void fused_kernel(const float* __restrict__ node0,
                             const float* __restrict__ node1,
                             const float* __restrict__ node2,
                             const float* __restrict__ rij,
                             const float* __restrict__ Wrad,
                             const float* __restrict__ U,
                             const float* __restrict__ V,
                             const float* __restrict__ Wg,
                             const int* __restrict__ idx_j,
                             float* __restrict__ out,
                             int N)
{
    extern __shared__ float sh[];
    float* sWrad = sh;                         // 11*8*32 = 2816
    float* sWm   = sWrad + 2816;               // U(3*1024) + V(8*1024) = 11264
    float* sWg   = sWm + 11264;                // 3*1024 = 3072
    float* sX    = sWg + 3072;                 // NWARPS * 27 * 32
    float* sY    = sX + NWARPS * 27 * 32;      // NWARPS * 32

    for (int i = threadIdx.x; i < 2816; i += blockDim.x) sWrad[i] = Wrad[i];
    for (int i = threadIdx.x; i < 3 * 1024; i += blockDim.x) sWm[i] = U[i];
    for (int i = threadIdx.x; i < 8 * 1024; i += blockDim.x) sWm[3 * 1024 + i] = V[i];
    for (int i = threadIdx.x; i < 3 * 1024; i += blockDim.x) sWg[i] = Wg[i];
    __syncthreads();

    int warp = threadIdx.x >> 5;
    int lane = threadIdx.x & 31;
    int n = blockIdx.x * NWARPS + warp;
    if (n >= N) return;

    // -------- Phase 1: edge aggregation (registers) --------
    float a0 = 0.0f;
    float a1[3] = {0.0f, 0.0f, 0.0f};
    float a2[9] = {0.0f, 0.0f, 0.0f, 0.0f, 0.0f, 0.0f, 0.0f, 0.0f, 0.0f};

    int beg = g_off[n];
    int end = g_off[n + 1];

    for (int k0 = beg; k0 < end; k0 += 32) {
        int myE = (k0 + lane < end) ? g_edge[k0 + lane] : 0;
        int cnt = min(32, end - k0);
        for (int kk = 0; kk < cnt; kk++) {
            int e = __shfl_sync(0xffffffff, myE, kk);

            float rx = rij[3 * e + 0];
            float ry = rij[3 * e + 1];
            float rz = rij[3 * e + 2];
            float dd = rx * rx + ry * ry + rz * rz + 1e-12f;
            float dist = sqrtf(dd);
            float inv = 1.0f / dist;
            float h0 = rx * inv, h1 = ry * inv, h2 = rz * inv;

            float u = fminf(dist * 0.2f, 1.0f);
            float fc = 0.5f * (__cosf(3.14159265358979323846f * u) + 1.0f);

            float w[11];
#pragma unroll
            for (int p = 0; p < 11; p++) w[p] = 0.0f;
#pragma unroll
            for (int b = 0; b < 8; b++) {
                float cb = 0.5f + (float)b * (4.5f / 7.0f);
                float dl = dist - cb;
                float rb = __expf(-4.0f * dl * dl) * fc;
#pragma unroll
                for (int p = 0; p < 11; p++) w[p] += rb * sWrad[(p * 8 + b) * 32 + lane];
            }

            int j = idx_j[e];
            float g0 = node0[j * 32 + lane];
            const float* p1 = node1 + (size_t)(j * 32 + lane) * 3;
            float g1x = p1[0], g1y = p1[1], g1z = p1[2];
            const float* p2 = node2 + (size_t)(j * 32 + lane) * 9;
            float g2[9];
#pragma unroll
            for (int k = 0; k < 9; k++) g2[k] = p2[k];

            float d1 = g1x * h0 + g1y * h1 + g1z * h2;
            float d2[3];
#pragma unroll
            for (int a = 0; a < 3; a++)
                d2[a] = g2[a * 3 + 0] * h0 + g2[a * 3 + 1] * h1 + g2[a * 3 + 2] * h2;
            float q = d2[0] * h0 + d2[1] * h1 + d2[2] * h2;

            a0 += g0 * w[0] + d1 * w[4] + q * w[9];

            float hh[3] = {h0, h1, h2};
            float g1v[3] = {g1x, g1y, g1z};
            float s01 = g0 * w[1] + d1 * w[6];
#pragma unroll
            for (int a = 0; a < 3; a++)
                a1[a] += s01 * hh[a] + g1v[a] * w[3] + d2[a] * w[8];

            float gw2 = g0 * w[2];
#pragma unroll
            for (int a = 0; a < 3; a++) {
                float pre = gw2 * hh[a] + g1v[a] * w[5] + d2[a] * w[10];
#pragma unroll
                for (int b = 0; b < 3; b++)
                    a2[a * 3 + b] += pre * hh[b] + g2[a * 3 + b] * w[7];
            }
        }
    }

    const float norm = 1.0f / 16.0f;
    a0 *= norm;
#pragma unroll
    for (int a = 0; a < 3; a++) a1[a] *= norm;
#pragma unroll
    for (int k = 0; k < 9; k++) a2[k] *= norm;

    // -------- Phase 2: self-interaction --------
    float* Xs = sX + warp * 27 * 32;

    float s1 = a1[0] * a1[0] + a1[1] * a1[1] + a1[2] * a1[2];
    float s2 = 0.0f;
#pragma unroll
    for (int k = 0; k < 9; k++) s2 += a2[k] * a2[k];
    float t[3];
#pragma unroll
    for (int b = 0; b < 3; b++)
        t[b] = a1[0] * a2[0 * 3 + b] + a1[1] * a2[1 * 3 + b] + a1[2] * a2[2 * 3 + b];
    float r[9];
#pragma unroll
    for (int a = 0; a < 3; a++)
#pragma unroll
        for (int b = 0; b < 3; b++)
            r[a * 3 + b] = a2[a * 3 + 0] * a2[0 * 3 + b]
                         + a2[a * 3 + 1] * a2[1 * 3 + b]
                         + a2[a * 3 + 2] * a2[2 * 3 + b];

    Xs[0 * 32 + lane] = a0;
    Xs[1 * 32 + lane] = s1;
    Xs[2 * 32 + lane] = s2;
#pragma unroll
    for (int a = 0; a < 3; a++) { Xs[(3 + a) * 32 + lane] = a1[a]; Xs[(6 + a) * 32 + lane] = t[a]; }
#pragma unroll
    for (int k = 0; k < 9; k++) { Xs[(9 + k) * 32 + lane] = a2[k]; Xs[(18 + k) * 32 + lane] = r[k]; }
    __syncwarp();

    int d = lane;
    float y0 = 0.0f;
    float y1[3] = {0.0f, 0.0f, 0.0f};
    float y2[9] = {0.0f, 0.0f, 0.0f, 0.0f, 0.0f, 0.0f, 0.0f, 0.0f, 0.0f};

#pragma unroll 4
    for (int c = 0; c < 32; c++) {
        int wi = c * 32 + d;
        float xa0 = Xs[c];
        float xs1 = Xs[32 + c];
        float xs2 = Xs[64 + c];

        y0 += xa0 * sWm[0 * 1024 + wi]
            + (xa0 * xa0) * sWm[3 * 1024 + wi]
            + xs1 * sWm[6 * 1024 + wi]
            + xs2 * sWm[9 * 1024 + wi];

        float wU1 = sWm[1 * 1024 + wi];
        float wV1 = sWm[4 * 1024 + wi];
        float wV5 = sWm[8 * 1024 + wi];
        float xa1[3];
#pragma unroll
        for (int a = 0; a < 3; a++) {
            xa1[a] = Xs[(3 + a) * 32 + c];
            float xt = Xs[(6 + a) * 32 + c];
            y1[a] += xa1[a] * wU1 + (xa0 * xa1[a]) * wV1 + xt * wV5;
        }

        float wU2 = sWm[2 * 1024 + wi];
        float wV2 = sWm[5 * 1024 + wi];
        float wV4 = sWm[7 * 1024 + wi];
        float wV7 = sWm[10 * 1024 + wi];
#pragma unroll
        for (int a = 0; a < 3; a++) {
#pragma unroll
            for (int b = 0; b < 3; b++) {
                int k = a * 3 + b;
                float xa2 = Xs[(9 + k) * 32 + c];
                float xr = Xs[(18 + k) * 32 + c];
                y2[k] += xa2 * wU2 + (xa0 * xa2) * wV2 + (xa1[a] * xa1[b]) * wV4 + xr * wV7;
            }
        }
    }

    // gates
    float* Ys = sY + warp * 32;
    Ys[d] = y0;
    __syncwarp();
    float gp0 = 0.0f, gp1 = 0.0f, gp2 = 0.0f;
#pragma unroll 4
    for (int c = 0; c < 32; c++) {
        float yc = Ys[c];
        gp0 += yc * sWg[0 * 1024 + c * 32 + d];
        gp1 += yc * sWg[1 * 1024 + c * 32 + d];
        gp2 += yc * sWg[2 * 1024 + c * 32 + d];
    }
    float gate0 = gp0 / (1.0f + __expf(-gp0));
    float gate1 = gp1 / (1.0f + __expf(-gp1));
    float gate2 = gp2 / (1.0f + __expf(-gp2));

    float* out0 = out;
    float* out1 = out + (size_t)N * 32;
    float* out2 = out + (size_t)N * 32 * 4;

    out0[n * 32 + d] = node0[n * 32 + d] + gate0;
    const float* n1p = node1 + (size_t)(n * 32 + d) * 3;
    float* o1p = out1 + (size_t)(n * 32 + d) * 3;
#pragma unroll
    for (int a = 0; a < 3; a++) o1p[a] = n1p[a] + y1[a] * gate1;
    const float* n2p = node2 + (size_t)(n * 32 + d) * 9;
    float* o2p = out2 + (size_t)(n * 32 + d) * 9;
#pragma unroll
    for (int k = 0; k < 9; k++) o2p[k] = n2p[k] + y2[k] * gate2;
}

// ---------------------------------------------------------------------------
extern "C" void kernel_launch(void* const* d_in, const int* in_sizes, int n_in,
                              void* d_out, int out_size)
{
    const float* node0 = (const float*)d_in[0];
    const float* node1 = (const float*)d_in[1];
    const float* node2 = (const float*)d_in[2];
    const float* rij   = (const float*)d_in[3];
    const float* Wrad  = (const float*)d_in[4];
    const float* U     = (const float*)d_in[5];
    const float* V     = (const float*)d_in[6];
    const float* Wg    = (const float*)d_in[7];
    const int*   idx_i = (const int*)d_in[8];
    const int*   idx_j = (const int*)d_in[9];
    float* out = (float*)d_out;

    int N = in_sizes[0] / 32;
    int E = in_sizes[8];

    int fused_smem = (2816 + 11264 + 3072 + NWARPS * 27 * 32 + NWARPS * 32) * (int)sizeof(float);
    cudaFuncSetAttribute(fused_kernel, cudaFuncAttributeMaxDynamicSharedMemorySize, fused_smem);

    zero_deg_kernel<<<(N + 255) / 256, 256>>>(N);
    hist_kernel<<<(E + 255) / 256, 256>>>(idx_i, E);
    scan_kernel<<<1, 1024>>>(N, E);
    scatter_kernel<<<(E + 255) / 256, 256>>>(idx_i, E);
    fused_kernel<<<(N + NWARPS - 1) / NWARPS, 32 * NWARPS, fused_smem>>>(
        node0, node1, node2, rij, Wrad, U, V, Wg, idx_j, out, N);
}